// round 4
// baseline (speedup 1.0000x reference)
#include <cuda_runtime.h>

#define BB  16
#define TQ  128
#define TK  256
#define DIN 64
#define HH  256
#define DV  256
#define NEGF (-1000000.0f)

// Scratch: projected queries [b][q][h], projected keys TRANSPOSED [b][h][k]
__device__ float g_qproj[BB * TQ * HH];     // 2 MB
__device__ float g_kprojT[BB * HH * TK];    // 4 MB

__device__ __forceinline__ float tanha(float x) {
    float y;
    asm("tanh.approx.f32 %0, %1;" : "=f"(y) : "f"(x));
    return y;
}

// ---------------------------------------------------------------------------
// Kernel 1: projections. Each CTA computes 4 rows of one projection (q or k),
// 256 threads = one hidden column each. W loads are shared across the 4 rows.
// k-proj is stored transposed: kT[b][h][k] (k fastest) so the main kernel's
// per-h loads are coalesced across threads (thread == k).
// ---------------------------------------------------------------------------
__global__ __launch_bounds__(256) void proj_kernel(
    const float* __restrict__ queries, const float* __restrict__ keys,
    const float* __restrict__ wq, const float* __restrict__ wk)
{
    const int tid = threadIdx.x;
    const int blk = blockIdx.x;
    __shared__ __align__(16) float ins[4 * DIN];   // 4 input rows x 64

    const float* W;
    const float* inbase;
    bool isQ = blk < (BB * TQ / 4);
    int b, r0;
    if (isQ) {
        b  = blk / (TQ / 4);
        r0 = (blk % (TQ / 4)) * 4;
        W  = wq;
        inbase = queries + (b * TQ + r0) * DIN;
    } else {
        int kb = blk - BB * TQ / 4;
        b  = kb / (TK / 4);
        r0 = (kb % (TK / 4)) * 4;
        W  = wk;
        inbase = keys + (b * TK + r0) * DIN;
    }
    // 4 rows x 64 = 256 contiguous floats
    ins[tid] = inbase[tid];
    __syncthreads();

    float a0 = 0.f, a1 = 0.f, a2 = 0.f, a3 = 0.f;
    #pragma unroll 4
    for (int d = 0; d < DIN; d++) {
        float w = W[d * HH + tid];          // coalesced, W is L1/L2-hot
        a0 = fmaf(ins[0 * DIN + d], w, a0);
        a1 = fmaf(ins[1 * DIN + d], w, a1);
        a2 = fmaf(ins[2 * DIN + d], w, a2);
        a3 = fmaf(ins[3 * DIN + d], w, a3);
    }

    if (isQ) {
        float* o = g_qproj + (b * TQ + r0) * HH + tid;
        o[0 * HH] = a0; o[1 * HH] = a1; o[2 * HH] = a2; o[3 * HH] = a3;
    } else {
        // kT[b][h=tid][k=r0..r0+3] : 4 contiguous floats per thread
        float4* o = (float4*)(g_kprojT + (size_t)b * HH * TK + tid * TK + r0);
        *o = make_float4(a0, a1, a2, a3);
    }
}

// ---------------------------------------------------------------------------
// Kernel 2: scores + masked softmax + attn @ V.
// CTA = (batch, tile of 4 q-rows). 256 threads; thread == one k (then one v).
// ---------------------------------------------------------------------------
__global__ __launch_bounds__(256) void attn_kernel(
    const float* __restrict__ values, const int* __restrict__ valid_lens,
    const float* __restrict__ wv, float* __restrict__ out)
{
    const int tid  = threadIdx.x;
    const int b    = blockIdx.x >> 5;          // 32 q-tiles per batch
    const int q0   = (blockIdx.x & 31) * 4;
    const int lane = tid & 31, wid = tid >> 5;

    __shared__ __align__(16) float qs[4][HH];
    __shared__ __align__(16) float wvs[HH];
    __shared__ __align__(16) float attn[4][TK];
    __shared__ float redm[4][8], reds[4][8];

    wvs[tid] = wv[tid];
    #pragma unroll
    for (int r = 0; r < 4; r++)
        qs[r][tid] = g_qproj[(b * TQ + q0 + r) * HH + tid];
    __syncthreads();

    // ---- scores: acc[r] = sum_h wv[h] * tanh(q[r][h] + k[h][tid]) ----
    const float* kT = g_kprojT + (size_t)b * HH * TK;
    float acc[4] = {0.f, 0.f, 0.f, 0.f};
    #pragma unroll 2
    for (int h = 0; h < HH; h += 4) {
        float k0 = kT[(h + 0) * TK + tid];     // coalesced, L2-hot
        float k1 = kT[(h + 1) * TK + tid];
        float k2 = kT[(h + 2) * TK + tid];
        float k3 = kT[(h + 3) * TK + tid];
        float4 wv4 = *(const float4*)&wvs[h];
        #pragma unroll
        for (int r = 0; r < 4; r++) {
            float4 q4 = *(const float4*)&qs[r][h];
            acc[r] = fmaf(wv4.x, tanha(q4.x + k0), acc[r]);
            acc[r] = fmaf(wv4.y, tanha(q4.y + k1), acc[r]);
            acc[r] = fmaf(wv4.z, tanha(q4.z + k2), acc[r]);
            acc[r] = fmaf(wv4.w, tanha(q4.w + k3), acc[r]);
        }
    }

    // ---- masked softmax over k (thread owns one k) ----
    const int vl = valid_lens[b];
    float s[4];
    #pragma unroll
    for (int r = 0; r < 4; r++) {
        s[r] = (tid < vl) ? acc[r] : NEGF;
        float mm = s[r];
        #pragma unroll
        for (int o = 16; o; o >>= 1) mm = fmaxf(mm, __shfl_xor_sync(0xffffffffu, mm, o));
        if (lane == 0) redm[r][wid] = mm;
    }
    __syncthreads();
    float p[4];
    #pragma unroll
    for (int r = 0; r < 4; r++) {
        float mm = redm[r][0];
        #pragma unroll
        for (int i = 1; i < 8; i++) mm = fmaxf(mm, redm[r][i]);
        p[r] = __expf(s[r] - mm);              // vl==0 -> all diffs 0 -> uniform
        float ss = p[r];
        #pragma unroll
        for (int o = 16; o; o >>= 1) ss += __shfl_xor_sync(0xffffffffu, ss, o);
        if (lane == 0) reds[r][wid] = ss;
    }
    __syncthreads();
    #pragma unroll
    for (int r = 0; r < 4; r++) {
        float ss = reds[r][0];
        #pragma unroll
        for (int i = 1; i < 8; i++) ss += reds[r][i];
        attn[r][tid] = p[r] * (1.0f / ss);
    }
    __syncthreads();

    // ---- out[r][v=tid] = sum_k attn[r][k] * V[k][tid] ----
    const float* V = values + (size_t)b * TK * DV;
    float o4[4] = {0.f, 0.f, 0.f, 0.f};
    #pragma unroll 2
    for (int k = 0; k < TK; k += 4) {
        float v0 = V[(k + 0) * DV + tid];      // coalesced, L2-hot
        float v1 = V[(k + 1) * DV + tid];
        float v2 = V[(k + 2) * DV + tid];
        float v3 = V[(k + 3) * DV + tid];
        #pragma unroll
        for (int r = 0; r < 4; r++) {
            float4 a4 = *(const float4*)&attn[r][k];
            o4[r] = fmaf(a4.x, v0, o4[r]);
            o4[r] = fmaf(a4.y, v1, o4[r]);
            o4[r] = fmaf(a4.z, v2, o4[r]);
            o4[r] = fmaf(a4.w, v3, o4[r]);
        }
    }
    #pragma unroll
    for (int r = 0; r < 4; r++)
        out[(b * TQ + q0 + r) * DV + tid] = o4[r];
}

extern "C" void kernel_launch(void* const* d_in, const int* in_sizes, int n_in,
                              void* d_out, int out_size)
{
    const float* queries    = (const float*)d_in[0];
    const float* keys       = (const float*)d_in[1];
    const float* values     = (const float*)d_in[2];
    const int*   valid_lens = (const int*)  d_in[3];
    const float* wq         = (const float*)d_in[4];
    const float* wk         = (const float*)d_in[5];
    const float* wv         = (const float*)d_in[6];
    float*       out        = (float*)d_out;

    proj_kernel<<<(BB * TQ + BB * TK) / 4, 256>>>(queries, keys, wq, wk);
    attn_kernel<<<BB * TQ / 4, 256>>>(values, valid_lens, wv, out);
}

// round 5
// speedup vs baseline: 1.0925x; 1.0925x over previous
#include <cuda_runtime.h>
#include <cstdint>

#define BB  16
#define TQ  128
#define TK  256
#define DIN 64
#define HH  256
#define DV  256
#define NEGF (-1000000.0f)

// Scratch: projected queries [b][q][h], projected keys TRANSPOSED [b][h][k]
__device__ float g_qproj[BB * TQ * HH];     // 2 MB
__device__ float g_kprojT[BB * HH * TK];    // 4 MB

__device__ __forceinline__ float tanha(float x) {
    float y;
    asm("tanh.approx.f32 %0, %1;" : "=f"(y) : "f"(x));
    return y;
}

__device__ __forceinline__ void cp16(uint32_t dst_smem, const void* src) {
    asm volatile("cp.async.ca.shared.global [%0], [%1], 16;\n"
                 :: "r"(dst_smem), "l"(src));
}

// ---------------------------------------------------------------------------
// Kernel 1: projections. Each CTA computes 8 rows of one projection (q or k),
// 256 threads = one hidden column each. W loads amortized over 8 rows.
// k-proj is stored transposed: kT[b][h][k] (k fastest).
// ---------------------------------------------------------------------------
__global__ __launch_bounds__(256) void proj_kernel(
    const float* __restrict__ queries, const float* __restrict__ keys,
    const float* __restrict__ wq, const float* __restrict__ wk)
{
    const int tid = threadIdx.x;
    const int blk = blockIdx.x;
    __shared__ __align__(16) float ins[8 * DIN];   // 8 input rows x 64

    const float* W;
    const float* inbase;
    bool isQ = blk < (BB * TQ / 8);
    int b, r0;
    if (isQ) {
        b  = blk / (TQ / 8);
        r0 = (blk % (TQ / 8)) * 8;
        W  = wq;
        inbase = queries + (b * TQ + r0) * DIN;
    } else {
        int kb = blk - BB * TQ / 8;
        b  = kb / (TK / 8);
        r0 = (kb % (TK / 8)) * 8;
        W  = wk;
        inbase = keys + (b * TK + r0) * DIN;
    }
    // 8 rows x 64 = 512 contiguous floats
    ins[tid]       = inbase[tid];
    ins[tid + 256] = inbase[tid + 256];
    __syncthreads();

    float a[8];
    #pragma unroll
    for (int r = 0; r < 8; r++) a[r] = 0.f;

    #pragma unroll 8
    for (int d = 0; d < DIN; d++) {
        float w = W[d * HH + tid];          // coalesced, L1-hot after wave 1
        #pragma unroll
        for (int r = 0; r < 8; r++)
            a[r] = fmaf(ins[r * DIN + d], w, a[r]);
    }

    if (isQ) {
        float* o = g_qproj + (b * TQ + r0) * HH + tid;
        #pragma unroll
        for (int r = 0; r < 8; r++) o[r * HH] = a[r];
    } else {
        // kT[b][h=tid][k=r0..r0+7] : 8 contiguous floats per thread
        float* o = g_kprojT + (size_t)b * HH * TK + tid * TK + r0;
        *(float4*)(o + 0) = make_float4(a[0], a[1], a[2], a[3]);
        *(float4*)(o + 4) = make_float4(a[4], a[5], a[6], a[7]);
    }
}

// ---------------------------------------------------------------------------
// Kernel 2: scores + masked softmax + attn @ V.
// CTA = (batch, tile of 4 q-rows). 256 threads; thread == one k (then one v).
// kT streamed through double-buffered smem via cp.async so MUFU never starves.
// ---------------------------------------------------------------------------
#define CHUNK_H 16
#define NCHUNK  (HH / CHUNK_H)   // 16

__global__ __launch_bounds__(256) void attn_kernel(
    const float* __restrict__ values, const int* __restrict__ valid_lens,
    const float* __restrict__ wv, float* __restrict__ out)
{
    const int tid  = threadIdx.x;
    const int b    = blockIdx.x >> 5;          // 32 q-tiles per batch
    const int q0   = (blockIdx.x & 31) * 4;
    const int lane = tid & 31, wid = tid >> 5;

    __shared__ __align__(16) float kbuf[2][CHUNK_H][TK];   // 32 KB
    __shared__ __align__(16) float qs[4][HH];              // 4 KB
    __shared__ __align__(16) float wvs[HH];                // 1 KB
    __shared__ __align__(16) float attnS[4][TK];           // 4 KB
    __shared__ float redm[4][8], reds[4][8];

    wvs[tid] = wv[tid];
    #pragma unroll
    for (int r = 0; r < 4; r++)
        qs[r][tid] = g_qproj[(b * TQ + q0 + r) * HH + tid];

    const float* kTb = g_kprojT + (size_t)b * HH * TK;

    // prefetch chunk 0
    {
        uint32_t base = (uint32_t)__cvta_generic_to_shared(&kbuf[0][0][0]);
        const float* src = kTb;
        #pragma unroll
        for (int j = 0; j < 4; j++) {
            int s = tid + 256 * j;             // 16B segment index, 0..1023
            cp16(base + s * 16, src + s * 4);
        }
        asm volatile("cp.async.commit_group;");
    }
    __syncthreads();   // qs/wvs visible

    float acc[4] = {0.f, 0.f, 0.f, 0.f};

    #pragma unroll 1
    for (int c = 0; c < NCHUNK; c++) {
        const int bufi = c & 1;
        if (c + 1 < NCHUNK) {
            uint32_t base = (uint32_t)__cvta_generic_to_shared(&kbuf[bufi ^ 1][0][0]);
            const float* src = kTb + (c + 1) * CHUNK_H * TK;
            #pragma unroll
            for (int j = 0; j < 4; j++) {
                int s = tid + 256 * j;
                cp16(base + s * 16, src + s * 4);
            }
            asm volatile("cp.async.commit_group;");
            asm volatile("cp.async.wait_group 1;");   // chunk c done
        } else {
            asm volatile("cp.async.wait_group 0;");
        }
        __syncthreads();

        #pragma unroll
        for (int hh = 0; hh < CHUNK_H; hh += 4) {
            const int h = c * CHUNK_H + hh;
            float k0 = kbuf[bufi][hh + 0][tid];
            float k1 = kbuf[bufi][hh + 1][tid];
            float k2 = kbuf[bufi][hh + 2][tid];
            float k3 = kbuf[bufi][hh + 3][tid];
            float4 wv4 = *(const float4*)&wvs[h];
            #pragma unroll
            for (int r = 0; r < 4; r++) {
                float4 q4 = *(const float4*)&qs[r][h];
                acc[r] = fmaf(wv4.x, tanha(q4.x + k0), acc[r]);
                acc[r] = fmaf(wv4.y, tanha(q4.y + k1), acc[r]);
                acc[r] = fmaf(wv4.z, tanha(q4.z + k2), acc[r]);
                acc[r] = fmaf(wv4.w, tanha(q4.w + k3), acc[r]);
            }
        }
        __syncthreads();   // buffer free for next prefetch
    }

    // ---- masked softmax over k (thread owns one k) ----
    const int vl = valid_lens[b];
    float s[4];
    #pragma unroll
    for (int r = 0; r < 4; r++) {
        s[r] = (tid < vl) ? acc[r] : NEGF;
        float mm = s[r];
        #pragma unroll
        for (int o = 16; o; o >>= 1) mm = fmaxf(mm, __shfl_xor_sync(0xffffffffu, mm, o));
        if (lane == 0) redm[r][wid] = mm;
    }
    __syncthreads();
    float p[4];
    #pragma unroll
    for (int r = 0; r < 4; r++) {
        float mm = redm[r][0];
        #pragma unroll
        for (int i = 1; i < 8; i++) mm = fmaxf(mm, redm[r][i]);
        p[r] = __expf(s[r] - mm);              // vl==0 -> all diffs 0 -> uniform
        float ss = p[r];
        #pragma unroll
        for (int o = 16; o; o >>= 1) ss += __shfl_xor_sync(0xffffffffu, ss, o);
        if (lane == 0) reds[r][wid] = ss;
    }
    __syncthreads();
    #pragma unroll
    for (int r = 0; r < 4; r++) {
        float ss = reds[r][0];
        #pragma unroll
        for (int i = 1; i < 8; i++) ss += reds[r][i];
        attnS[r][tid] = p[r] * (1.0f / ss);
    }
    __syncthreads();

    // ---- out[r][v=tid] = sum_k attn[r][k] * V[k][tid] ----
    // register double-buffered V loads (coalesced, L2-hot)
    const float* Vp = values + (size_t)b * TK * DV + tid;
    float o4[4] = {0.f, 0.f, 0.f, 0.f};
    float n0 = Vp[0 * DV], n1 = Vp[1 * DV], n2 = Vp[2 * DV], n3 = Vp[3 * DV];
    #pragma unroll 2
    for (int k = 0; k < TK; k += 4) {
        float v0 = n0, v1 = n1, v2 = n2, v3 = n3;
        if (k + 4 < TK) {
            n0 = Vp[(k + 4) * DV]; n1 = Vp[(k + 5) * DV];
            n2 = Vp[(k + 6) * DV]; n3 = Vp[(k + 7) * DV];
        }
        #pragma unroll
        for (int r = 0; r < 4; r++) {
            float4 a4 = *(const float4*)&attnS[r][k];
            o4[r] = fmaf(a4.x, v0, o4[r]);
            o4[r] = fmaf(a4.y, v1, o4[r]);
            o4[r] = fmaf(a4.z, v2, o4[r]);
            o4[r] = fmaf(a4.w, v3, o4[r]);
        }
    }
    #pragma unroll
    for (int r = 0; r < 4; r++)
        out[(b * TQ + q0 + r) * DV + tid] = o4[r];
}

extern "C" void kernel_launch(void* const* d_in, const int* in_sizes, int n_in,
                              void* d_out, int out_size)
{
    const float* queries    = (const float*)d_in[0];
    const float* keys       = (const float*)d_in[1];
    const float* values     = (const float*)d_in[2];
    const int*   valid_lens = (const int*)  d_in[3];
    const float* wq         = (const float*)d_in[4];
    const float* wk         = (const float*)d_in[5];
    const float* wv         = (const float*)d_in[6];
    float*       out        = (float*)d_out;

    proj_kernel<<<BB * (TQ + TK) / 8, 256>>>(queries, keys, wq, wk);
    attn_kernel<<<BB * TQ / 4, 256>>>(values, valid_lens, wv, out);
}

// round 8
// speedup vs baseline: 1.3954x; 1.2772x over previous
#include <cuda_runtime.h>
#include <cstdint>

#define BB  16
#define TQ  128
#define TK  256
#define DIN 64
#define HH  256
#define DV  256
#define NEGF (-1000000.0f)

// Scratch: projected queries [b][q][h], projected keys TRANSPOSED [b][h][k]
__device__ float g_qproj[BB * TQ * HH];     // 2 MB
__device__ float g_kprojT[BB * HH * TK];    // 4 MB

__device__ __forceinline__ float tanha(float x) {
    float y;
    asm("tanh.approx.f32 %0, %1;" : "=f"(y) : "f"(x));
    return y;
}

__device__ __forceinline__ void cp16(uint32_t dst_smem, const void* src) {
    asm volatile("cp.async.ca.shared.global [%0], [%1], 16;\n"
                 :: "r"(dst_smem), "l"(src));
}

// ---------------------------------------------------------------------------
// Kernel 1: projections. Each CTA computes 8 rows of one projection (q or k),
// 256 threads = one hidden column each. W loads amortized over 8 rows.
// k-proj is stored transposed: kT[b][h][k] (k fastest).
// ---------------------------------------------------------------------------
__global__ __launch_bounds__(256) void proj_kernel(
    const float* __restrict__ queries, const float* __restrict__ keys,
    const float* __restrict__ wq, const float* __restrict__ wk)
{
    const int tid = threadIdx.x;
    const int blk = blockIdx.x;
    __shared__ __align__(16) float ins[8 * DIN];   // 8 input rows x 64

    const float* W;
    const float* inbase;
    bool isQ = blk < (BB * TQ / 8);
    int b, r0;
    if (isQ) {
        b  = blk / (TQ / 8);
        r0 = (blk % (TQ / 8)) * 8;
        W  = wq;
        inbase = queries + (b * TQ + r0) * DIN;
    } else {
        int kb = blk - BB * TQ / 8;
        b  = kb / (TK / 8);
        r0 = (kb % (TK / 8)) * 8;
        W  = wk;
        inbase = keys + (b * TK + r0) * DIN;
    }
    ins[tid]       = inbase[tid];
    ins[tid + 256] = inbase[tid + 256];
    __syncthreads();

    float a[8];
    #pragma unroll
    for (int r = 0; r < 8; r++) a[r] = 0.f;

    #pragma unroll 8
    for (int d = 0; d < DIN; d++) {
        float w = W[d * HH + tid];
        #pragma unroll
        for (int r = 0; r < 8; r++)
            a[r] = fmaf(ins[r * DIN + d], w, a[r]);
    }

    if (isQ) {
        float* o = g_qproj + (b * TQ + r0) * HH + tid;
        #pragma unroll
        for (int r = 0; r < 8; r++) o[r * HH] = a[r];
    } else {
        float* o = g_kprojT + (size_t)b * HH * TK + tid * TK + r0;
        *(float4*)(o + 0) = make_float4(a[0], a[1], a[2], a[3]);
        *(float4*)(o + 4) = make_float4(a[4], a[5], a[6], a[7]);
    }
}

// ---------------------------------------------------------------------------
// Kernel 2: scores + masked softmax + attn @ V.
// CTA = (batch, tile of 4 q-rows). 256 threads; thread == one k (then one v).
// kT double-buffered through smem via cp.async. Warps whose keys are all
// masked (32*wid >= vl) skip the tanh block entirely: masked scores become
// NEG and softmax maps them to exactly 0, matching the reference bit-wise.
// ---------------------------------------------------------------------------
#define CHUNK_H 16
#define NCHUNK  (HH / CHUNK_H)   // 16

__global__ __launch_bounds__(256) void attn_kernel(
    const float* __restrict__ values, const int* __restrict__ valid_lens,
    const float* __restrict__ wv, float* __restrict__ out)
{
    const int tid  = threadIdx.x;
    const int b    = blockIdx.x >> 5;          // 32 q-tiles per batch
    const int q0   = (blockIdx.x & 31) * 4;
    const int lane = tid & 31, wid = tid >> 5;

    __shared__ __align__(16) float kbuf[2][CHUNK_H][TK];   // 32 KB
    __shared__ __align__(16) float qs[4][HH];              // 4 KB
    __shared__ __align__(16) float wvs[HH];                // 1 KB
    __shared__ __align__(16) float attnS[4][TK];           // 4 KB
    __shared__ float redm[4][8], reds[4][8];

    const int vl = valid_lens[b];
    const bool active = (tid < vl);            // warp-uniform false for tail warps

    wvs[tid] = wv[tid];
    #pragma unroll
    for (int r = 0; r < 4; r++)
        qs[r][tid] = g_qproj[(b * TQ + q0 + r) * HH + tid];

    const float* kTb = g_kprojT + (size_t)b * HH * TK;

    // prefetch chunk 0
    {
        uint32_t base = (uint32_t)__cvta_generic_to_shared(&kbuf[0][0][0]);
        #pragma unroll
        for (int j = 0; j < 4; j++) {
            int s = tid + 256 * j;             // 16B segment index, 0..1023
            cp16(base + s * 16, kTb + s * 4);
        }
        asm volatile("cp.async.commit_group;");
    }
    __syncthreads();   // qs/wvs visible

    float acc[4] = {0.f, 0.f, 0.f, 0.f};

    #pragma unroll 1
    for (int c = 0; c < NCHUNK; c++) {
        const int bufi = c & 1;
        if (c + 1 < NCHUNK) {
            uint32_t base = (uint32_t)__cvta_generic_to_shared(&kbuf[bufi ^ 1][0][0]);
            const float* src = kTb + (c + 1) * CHUNK_H * TK;
            #pragma unroll
            for (int j = 0; j < 4; j++) {
                int s = tid + 256 * j;
                cp16(base + s * 16, src + s * 4);
            }
            asm volatile("cp.async.commit_group;");
            asm volatile("cp.async.wait_group 1;");   // chunk c landed
        } else {
            asm volatile("cp.async.wait_group 0;");
        }
        __syncthreads();

        if (active) {
            #pragma unroll
            for (int hh = 0; hh < CHUNK_H; hh += 4) {
                const int h = c * CHUNK_H + hh;
                float k0 = kbuf[bufi][hh + 0][tid];
                float k1 = kbuf[bufi][hh + 1][tid];
                float k2 = kbuf[bufi][hh + 2][tid];
                float k3 = kbuf[bufi][hh + 3][tid];
                float4 wv4 = *(const float4*)&wvs[h];
                #pragma unroll
                for (int r = 0; r < 4; r++) {
                    float4 q4 = *(const float4*)&qs[r][h];
                    acc[r] = fmaf(wv4.x, tanha(q4.x + k0), acc[r]);
                    acc[r] = fmaf(wv4.y, tanha(q4.y + k1), acc[r]);
                    acc[r] = fmaf(wv4.z, tanha(q4.z + k2), acc[r]);
                    acc[r] = fmaf(wv4.w, tanha(q4.w + k3), acc[r]);
                }
            }
        }
        __syncthreads();   // buffer free for next prefetch
    }

    // ---- masked softmax over k (thread owns one k) ----
    float s[4];
    #pragma unroll
    for (int r = 0; r < 4; r++) {
        s[r] = active ? acc[r] : NEGF;
        float mm = s[r];
        #pragma unroll
        for (int o = 16; o; o >>= 1) mm = fmaxf(mm, __shfl_xor_sync(0xffffffffu, mm, o));
        if (lane == 0) redm[r][wid] = mm;
    }
    __syncthreads();
    float p[4];
    #pragma unroll
    for (int r = 0; r < 4; r++) {
        float mm = redm[r][0];
        #pragma unroll
        for (int i = 1; i < 8; i++) mm = fmaxf(mm, redm[r][i]);
        p[r] = __expf(s[r] - mm);              // vl==0 -> all diffs 0 -> uniform
        float ss = p[r];
        #pragma unroll
        for (int o = 16; o; o >>= 1) ss += __shfl_xor_sync(0xffffffffu, ss, o);
        if (lane == 0) reds[r][wid] = ss;
    }
    __syncthreads();
    #pragma unroll
    for (int r = 0; r < 4; r++) {
        float ss = reds[r][0];
        #pragma unroll
        for (int i = 1; i < 8; i++) ss += reds[r][i];
        attnS[r][tid] = p[r] * (1.0f / ss);
    }
    __syncthreads();

    // ---- out[r][v=tid] = sum_k attn[r][k] * V[k][tid] ----
    // Masked attn weights are exactly 0.0 (exp(-1e6-mm) underflows), so only
    // k < ceil(vl/4)*4 contribute — except vl==0 (uniform weights): do all.
    const int kend = (vl == 0) ? TK : min(TK, (vl + 3) & ~3);
    const float* Vp = values + (size_t)b * TK * DV + tid;
    float o4[4] = {0.f, 0.f, 0.f, 0.f};
    float n0 = Vp[0 * DV], n1 = Vp[1 * DV], n2 = Vp[2 * DV], n3 = Vp[3 * DV];
    #pragma unroll 2
    for (int k = 0; k < kend; k += 4) {
        float v0 = n0, v1 = n1, v2 = n2, v3 = n3;
        if (k + 4 < kend) {
            n0 = Vp[(k + 4) * DV]; n1 = Vp[(k + 5) * DV];
            n2 = Vp[(k + 6) * DV]; n3 = Vp[(k + 7) * DV];
        }
        #pragma unroll
        for (int r = 0; r < 4; r++) {
            float4 a4 = *(const float4*)&attnS[r][k];
            o4[r] = fmaf(a4.x, v0, o4[r]);
            o4[r] = fmaf(a4.y, v1, o4[r]);
            o4[r] = fmaf(a4.z, v2, o4[r]);
            o4[r] = fmaf(a4.w, v3, o4[r]);
        }
    }
    #pragma unroll
    for (int r = 0; r < 4; r++)
        out[(b * TQ + q0 + r) * DV + tid] = o4[r];
}

extern "C" void kernel_launch(void* const* d_in, const int* in_sizes, int n_in,
                              void* d_out, int out_size)
{
    const float* queries    = (const float*)d_in[0];
    const float* keys       = (const float*)d_in[1];
    const float* values     = (const float*)d_in[2];
    const int*   valid_lens = (const int*)  d_in[3];
    const float* wq         = (const float*)d_in[4];
    const float* wk         = (const float*)d_in[5];
    const float* wv         = (const float*)d_in[6];
    float*       out        = (float*)d_out;

    proj_kernel<<<BB * (TQ + TK) / 8, 256>>>(queries, keys, wq, wk);
    attn_kernel<<<BB * TQ / 4, 256>>>(values, valid_lens, wv, out);
}